// round 2
// baseline (speedup 1.0000x reference)
#include <cuda_runtime.h>
#include <math.h>

#define FULL 0xffffffffu

static constexpr int M  = 6;
static constexpr int T  = 30;
static constexpr int L  = 10;
static constexpr int NL = 10;
static constexpr int P  = 50;
static constexpr int WARPS = 16;   // warps per block (512 threads)

__device__ float g_acc[8];

__device__ __forceinline__ float warp_sum(float v) {
#pragma unroll
    for (int o = 16; o; o >>= 1) v += __shfl_xor_sync(FULL, v, o);
    return v;
}
__device__ __forceinline__ float warp_max(float v) {
#pragma unroll
    for (int o = 16; o; o >>= 1) v = fmaxf(v, __shfl_xor_sync(FULL, v, o));
    return v;
}
__device__ __forceinline__ float smooth_l1(float x) {
    float ax = fabsf(x);
    return ax < 1.f ? 0.5f * ax * ax : ax - 0.5f;
}

__global__ void zero_kernel() {
    if (threadIdx.x < 8) g_acc[threadIdx.x] = 0.f;
}

__global__ void fin_kernel(float* __restrict__ out) {
    if (threadIdx.x == 0) {
        out[0] = g_acc[0] / fmaxf(g_acc[1], 1.f);  // cls_loss
        out[1] = 1.f;                              // constant
        out[2] = g_acc[2];                         // reg_loss
        out[3] = g_acc[3];                         // num_reg
        out[4] = g_acc[4];                         // lane_cls_loss
        out[5] = g_acc[5];                         // num_lane_cls
        out[6] = g_acc[6];                         // lane_off_loss
        out[7] = g_acc[7];                         // num_lane_off
    }
}

__global__ void __launch_bounds__(32 * WARPS)
pred_loss_kernel(const float* __restrict__ cls,
                 const float* __restrict__ reg,
                 const float* __restrict__ lane_cls,
                 const float* __restrict__ gt_preds,
                 const float* __restrict__ rot,
                 const float* __restrict__ orig,
                 const float* __restrict__ lane_feats,
                 const int* __restrict__ has_preds,   // bool widened to 4-byte
                 const int* __restrict__ lane_labels,
                 int B)
{
    __shared__ float  s_acc[8];
    __shared__ float2 s_w[WARPS][P];

    const int lane = threadIdx.x & 31;
    const int wid  = threadIdx.x >> 5;
    const int b    = blockIdx.x * WARPS + wid;

    if (threadIdx.x < 8) s_acc[threadIdx.x] = 0.f;
    __syncthreads();

    if (b < B) {
        const int  t  = lane;
        const bool tv = (t < T);

        // --- has_preds / last index / mask --------------------------------
        // 4-byte load + nonzero test: correct for both int32(1) and
        // float32(1.0f = 0x3F800000) widenings of the JAX bool.
        bool hp = tv && (has_preds[b * T + (tv ? t : 0)] != 0);
        unsigned bits = __ballot_sync(FULL, hp);
        int   nhas    = __popc(bits);
        int   last_i  = 31 - __clz(bits | 1u);   // t=0 always set per setup
        float maskf   = (bits & ~1u) ? 1.f : 0.f;

        float2 gt = make_float2(0.f, 0.f);
        if (tv) gt = ((const float2*)gt_preds)[b * T + t];

        // --- per-mode loop: cls_tar (argmin total sqdist), min_idx (end dist)
        float rmx[M], rmy[M];
        float best_tot = INFINITY; int cls_tar = 0;
        float best_end = INFINITY; int min_idx = 0;
#pragma unroll
        for (int m = 0; m < M; m++) {
            float2 r = make_float2(0.f, 0.f);
            if (tv) r = ((const float2*)reg)[(b * M + m) * T + t];
            rmx[m] = r.x; rmy[m] = r.y;
            float dx = r.x - gt.x, dy = r.y - gt.y;
            float d2 = tv ? (dx * dx + dy * dy) : 0.f;
            float e2 = __shfl_sync(FULL, d2, last_i);   // end-point sqdist
            float s  = warp_sum(d2);                    // total sqdist
            if (s  < best_tot) { best_tot = s;  cls_tar = m; }
            if (e2 < best_end) { best_end = e2; min_idx = m; }
        }
        // reg_sel = reg[b, min_idx, t]
        float rsx = rmx[0], rsy = rmy[0];
#pragma unroll
        for (int m = 1; m < M; m++) if (min_idx == m) { rsx = rmx[m]; rsy = rmy[m]; }

        // --- cls log-softmax NLL ------------------------------------------
        float cv  = (lane < M) ? cls[b * M + lane] : -INFINITY;
        float cmx = warp_max(cv);
        float cex = (lane < M) ? __expf(cv - cmx) : 0.f;
        float cse = warp_sum(cex);
        float ctar = __shfl_sync(FULL, cv, cls_tar);
        float nll  = -(ctar - cmx - __logf(cse));

        // --- lane cls log-softmax NLL -------------------------------------
        int   label  = lane_labels[b];
        bool  valid  = (label != 90);
        int   lab    = valid ? label : 0;
        float validf = valid ? 1.f : 0.f;
        float lv  = (lane < L) ? lane_cls[b * L + lane] : -INFINITY;
        float lmx = warp_max(lv);
        float lex = (lane < L) ? __expf(lv - lmx) : 0.f;
        float lse = warp_sum(lex);
        float ltar = __shfl_sync(FULL, lv, lab);
        float lane_nll = -(ltar - lmx - __logf(lse));

        // --- rotate selected lane points into world frame -> shared -------
        float4 rr = ((const float4*)rot)[b];      // rot[0][0],rot[0][1],rot[1][0],rot[1][1]
        float2 og = ((const float2*)orig)[b];
        const float2* lf = ((const float2*)lane_feats) + (size_t)(b * NL + lab) * P;
#pragma unroll
        for (int p = lane; p < P; p += 32) {
            float2 q = lf[p];
            s_w[wid][p] = make_float2(fmaf(q.x, rr.x, fmaf(q.y, rr.z, og.x)),
                                      fmaf(q.x, rr.y, fmaf(q.y, rr.w, og.y)));
        }
        __syncwarp(FULL);

        // --- min over P points: d_reg, d_gt (uniform broadcast LDS) -------
        float minr = INFINITY, ming = INFINITY;
#pragma unroll
        for (int p = 0; p < P; p++) {
            float2 w = s_w[wid][p];
            float dxr = w.x - rsx, dyr = w.y - rsy;
            minr = fminf(minr, fmaf(dxr, dxr, dyr * dyr));
            float dxg = w.x - gt.x, dyg = w.y - gt.y;
            ming = fminf(ming, fmaf(dxg, dxg, dyg * dyg));
        }
        float diff    = sqrtf(minr) - sqrtf(ming);
        float contrib = hp ? fmaxf(diff, 0.f) : 0.f;   // diff*(d_reg>=d_gt)*hasf

        // --- smooth-L1 regression loss ------------------------------------
        float wreg = hp ? maskf : 0.f;
        float regl = (smooth_l1(rsx - gt.x) + smooth_l1(rsy - gt.y)) * wreg;

        float sum_c = warp_sum(contrib);
        float sum_r = warp_sum(regl);

        if (lane == 0) {
            float per = sum_c / fmaxf((float)nhas, 1.f);
            atomicAdd(&s_acc[0], nll * maskf);
            atomicAdd(&s_acc[1], maskf);
            atomicAdd(&s_acc[2], sum_r);
            atomicAdd(&s_acc[3], (float)nhas * maskf);
            atomicAdd(&s_acc[4], lane_nll * (float)(lab + 1) * validf);
            atomicAdd(&s_acc[5], validf);
            atomicAdd(&s_acc[6], per * validf * maskf);
            atomicAdd(&s_acc[7], validf * maskf);
        }
    }
    __syncthreads();
    if (threadIdx.x < 8) atomicAdd(&g_acc[threadIdx.x], s_acc[threadIdx.x]);
}

extern "C" void kernel_launch(void* const* d_in, const int* in_sizes, int n_in,
                              void* d_out, int out_size)
{
    const float* cls        = (const float*)d_in[0];
    const float* reg        = (const float*)d_in[1];
    const float* lane_cls   = (const float*)d_in[2];
    const float* gt_preds   = (const float*)d_in[3];
    const float* rot        = (const float*)d_in[4];
    const float* orig       = (const float*)d_in[5];
    const float* lane_feats = (const float*)d_in[6];
    const int*   has_preds  = (const int*)d_in[7];
    const int*   lane_lab   = (const int*)d_in[8];

    int B = in_sizes[0] / M;   // cls is (B, M)

    zero_kernel<<<1, 32>>>();
    int blocks = (B + WARPS - 1) / WARPS;
    pred_loss_kernel<<<blocks, 32 * WARPS>>>(cls, reg, lane_cls, gt_preds, rot,
                                             orig, lane_feats, has_preds,
                                             lane_lab, B);
    fin_kernel<<<1, 32>>>((float*)d_out);
}

// round 3
// speedup vs baseline: 1.0331x; 1.0331x over previous
#include <cuda_runtime.h>
#include <math.h>

#define FULL 0xffffffffu

static constexpr int M  = 6;
static constexpr int T  = 30;
static constexpr int L  = 10;
static constexpr int NL = 10;
static constexpr int P  = 50;
static constexpr int WARPS = 16;   // warps per block (512 threads)

__device__ float    g_acc[8];      // zero-init at module load; reset by last block
__device__ unsigned g_ticket = 0;

__device__ __forceinline__ float warp_sum(float v) {
#pragma unroll
    for (int o = 16; o; o >>= 1) v += __shfl_xor_sync(FULL, v, o);
    return v;
}
__device__ __forceinline__ float warp_max(float v) {
#pragma unroll
    for (int o = 16; o; o >>= 1) v = fmaxf(v, __shfl_xor_sync(FULL, v, o));
    return v;
}
__device__ __forceinline__ float smooth_l1(float x) {
    float ax = fabsf(x);
    return ax < 1.f ? 0.5f * ax * ax : ax - 0.5f;
}

__device__ __forceinline__ unsigned long long pack2(float lo, float hi) {
    unsigned long long r;
    asm("mov.b64 %0, {%1, %2};" : "=l"(r) : "f"(lo), "f"(hi));
    return r;
}
__device__ __forceinline__ void unpack2(float& lo, float& hi, unsigned long long v) {
    asm("mov.b64 {%0, %1}, %2;" : "=f"(lo), "=f"(hi) : "l"(v));
}
__device__ __forceinline__ unsigned long long add2(unsigned long long a, unsigned long long b) {
    unsigned long long r;
    asm("add.rn.f32x2 %0, %1, %2;" : "=l"(r) : "l"(a), "l"(b));
    return r;
}
__device__ __forceinline__ unsigned long long mul2(unsigned long long a, unsigned long long b) {
    unsigned long long r;
    asm("mul.rn.f32x2 %0, %1, %2;" : "=l"(r) : "l"(a), "l"(b));
    return r;
}
__device__ __forceinline__ unsigned long long fma2(unsigned long long a, unsigned long long b,
                                                   unsigned long long c) {
    unsigned long long r;
    asm("fma.rn.f32x2 %0, %1, %2, %3;" : "=l"(r) : "l"(a), "l"(b), "l"(c));
    return r;
}

__global__ void __launch_bounds__(32 * WARPS)
pred_loss_kernel(const float* __restrict__ cls,
                 const float* __restrict__ reg,
                 const float* __restrict__ lane_cls,
                 const float* __restrict__ gt_preds,
                 const float* __restrict__ rot,
                 const float* __restrict__ orig,
                 const float* __restrict__ lane_feats,
                 const int* __restrict__ has_preds,   // bool widened to 4-byte
                 const int* __restrict__ lane_labels,
                 float* __restrict__ out,
                 int B)
{
    __shared__ float      s_acc[8];
    __shared__ ulonglong2 s_w[WARPS][P];   // .x = (wx,wx)  .y = (wy,wy)

    const int lane = threadIdx.x & 31;
    const int wid  = threadIdx.x >> 5;
    const int b    = blockIdx.x * WARPS + wid;

    if (threadIdx.x < 8) s_acc[threadIdx.x] = 0.f;
    __syncthreads();

    if (b < B) {
        const int  t  = lane;
        const bool tv = (t < T);

        // --- has_preds / last index / mask --------------------------------
        bool hp = tv && (has_preds[b * T + (tv ? t : 0)] != 0);
        unsigned bits = __ballot_sync(FULL, hp);
        int   nhas    = __popc(bits);
        int   last_i  = 31 - __clz(bits | 1u);   // t=0 always set per setup
        float maskf   = (bits & ~1u) ? 1.f : 0.f;

        float2 gt = make_float2(0.f, 0.f);
        if (tv) gt = ((const float2*)gt_preds)[b * T + t];

        // --- per-mode: cls_tar (argmin total sqdist), local end-dists -----
        float rmx[M], rmy[M], d2m[M];
        float best_tot = INFINITY; int cls_tar = 0;
#pragma unroll
        for (int m = 0; m < M; m++) {
            float2 r = make_float2(0.f, 0.f);
            if (tv) r = ((const float2*)reg)[(b * M + m) * T + t];
            rmx[m] = r.x; rmy[m] = r.y;
            float dx = r.x - gt.x, dy = r.y - gt.y;
            float d2 = tv ? fmaf(dx, dx, dy * dy) : 0.f;
            d2m[m] = d2;
            float s = warp_sum(d2);
            if (s < best_tot) { best_tot = s; cls_tar = m; }
        }
        // end-point argmin: lane last_i holds the end d2 for every mode
        float best_end = d2m[0]; int my_min = 0;
#pragma unroll
        for (int m = 1; m < M; m++)
            if (d2m[m] < best_end) { best_end = d2m[m]; my_min = m; }
        int min_idx = __shfl_sync(FULL, my_min, last_i);

        // reg_sel = reg[b, min_idx, t]
        float rsx = rmx[0], rsy = rmy[0];
#pragma unroll
        for (int m = 1; m < M; m++) if (min_idx == m) { rsx = rmx[m]; rsy = rmy[m]; }

        // --- cls log-softmax NLL ------------------------------------------
        float cv  = (lane < M) ? cls[b * M + lane] : -INFINITY;
        float cmx = warp_max(cv);
        float cex = (lane < M) ? __expf(cv - cmx) : 0.f;
        float cse = warp_sum(cex);
        float ctar = __shfl_sync(FULL, cv, cls_tar);
        float nll  = -(ctar - cmx - __logf(cse));

        // --- lane cls log-softmax NLL -------------------------------------
        int   label  = lane_labels[b];
        bool  valid  = (label != 90);
        int   lab    = valid ? label : 0;
        float validf = valid ? 1.f : 0.f;
        float lv  = (lane < L) ? lane_cls[b * L + lane] : -INFINITY;
        float lmx = warp_max(lv);
        float lex = (lane < L) ? __expf(lv - lmx) : 0.f;
        float lse = warp_sum(lex);
        float ltar = __shfl_sync(FULL, lv, lab);
        float lane_nll = -(ltar - lmx - __logf(lse));

        // --- rotate selected lane points into world frame -> shared -------
        float4 rr = ((const float4*)rot)[b];
        float2 og = ((const float2*)orig)[b];
        const float2* lf = ((const float2*)lane_feats) + (size_t)(b * NL + lab) * P;
#pragma unroll
        for (int p = lane; p < P; p += 32) {
            float2 q = lf[p];
            float wx = fmaf(q.x, rr.x, fmaf(q.y, rr.z, og.x));
            float wy = fmaf(q.x, rr.y, fmaf(q.y, rr.w, og.y));
            s_w[wid][p] = make_ulonglong2(pack2(wx, wx), pack2(wy, wy));
        }
        __syncwarp(FULL);

        // --- min over P points: packed (d_reg2, d_gt2) via f32x2 ----------
        unsigned long long nrx2 = pack2(-rsx, -gt.x);
        unsigned long long nry2 = pack2(-rsy, -gt.y);
        float minr = INFINITY, ming = INFINITY;
#pragma unroll
        for (int p = 0; p < P; p++) {
            ulonglong2 w = s_w[wid][p];
            unsigned long long dx2 = add2(w.x, nrx2);
            unsigned long long dy2 = add2(w.y, nry2);
            unsigned long long d2  = fma2(dx2, dx2, mul2(dy2, dy2));
            float lo, hi; unpack2(lo, hi, d2);
            minr = fminf(minr, lo);
            ming = fminf(ming, hi);
        }
        float diff    = sqrtf(minr) - sqrtf(ming);
        float contrib = hp ? fmaxf(diff, 0.f) : 0.f;   // diff*(d_reg>=d_gt)*hasf

        // --- smooth-L1 regression loss ------------------------------------
        float wreg = hp ? maskf : 0.f;
        float regl = (smooth_l1(rsx - gt.x) + smooth_l1(rsy - gt.y)) * wreg;

        float sum_c = warp_sum(contrib);
        float sum_r = warp_sum(regl);

        if (lane == 0) {
            float per = sum_c / fmaxf((float)nhas, 1.f);
            atomicAdd(&s_acc[0], nll * maskf);
            atomicAdd(&s_acc[1], maskf);
            atomicAdd(&s_acc[2], sum_r);
            atomicAdd(&s_acc[3], (float)nhas * maskf);
            atomicAdd(&s_acc[4], lane_nll * (float)(lab + 1) * validf);
            atomicAdd(&s_acc[5], validf);
            atomicAdd(&s_acc[6], per * validf * maskf);
            atomicAdd(&s_acc[7], validf * maskf);
        }
    }
    __syncthreads();

    // --- block partial -> global, ticket, last block finalizes ------------
    if (threadIdx.x < 8) {
        atomicAdd(&g_acc[threadIdx.x], s_acc[threadIdx.x]);
        __threadfence();
    }
    __syncthreads();

    __shared__ bool s_last;
    if (threadIdx.x == 0) {
        unsigned t = atomicAdd(&g_ticket, 1u);
        s_last = (t == gridDim.x - 1);
    }
    __syncthreads();

    if (s_last) {
        if (threadIdx.x < 8) {
            __threadfence();
            s_acc[threadIdx.x] = atomicAdd(&g_acc[threadIdx.x], 0.f);  // coherent read
        }
        __syncthreads();
        if (threadIdx.x == 0) {
            out[0] = s_acc[0] / fmaxf(s_acc[1], 1.f);  // cls_loss
            out[1] = 1.f;
            out[2] = s_acc[2];                         // reg_loss
            out[3] = s_acc[3];                         // num_reg
            out[4] = s_acc[4];                         // lane_cls_loss
            out[5] = s_acc[5];                         // num_lane_cls
            out[6] = s_acc[6];                         // lane_off_loss
            out[7] = s_acc[7];                         // num_lane_off
        }
        // reset for next graph replay
        if (threadIdx.x < 8) atomicExch(&g_acc[threadIdx.x], 0.f);
        __syncthreads();
        if (threadIdx.x == 0) {
            __threadfence();
            atomicExch(&g_ticket, 0u);
        }
    }
}

extern "C" void kernel_launch(void* const* d_in, const int* in_sizes, int n_in,
                              void* d_out, int out_size)
{
    const float* cls        = (const float*)d_in[0];
    const float* reg        = (const float*)d_in[1];
    const float* lane_cls   = (const float*)d_in[2];
    const float* gt_preds   = (const float*)d_in[3];
    const float* rot        = (const float*)d_in[4];
    const float* orig       = (const float*)d_in[5];
    const float* lane_feats = (const float*)d_in[6];
    const int*   has_preds  = (const int*)d_in[7];
    const int*   lane_lab   = (const int*)d_in[8];

    int B = in_sizes[0] / M;   // cls is (B, M)
    int blocks = (B + WARPS - 1) / WARPS;
    pred_loss_kernel<<<blocks, 32 * WARPS>>>(cls, reg, lane_cls, gt_preds, rot,
                                             orig, lane_feats, has_preds,
                                             lane_lab, (float*)d_out, B);
}

// round 4
// speedup vs baseline: 1.1092x; 1.0737x over previous
#include <cuda_runtime.h>
#include <math.h>

#define FULL 0xffffffffu

static constexpr int M  = 6;
static constexpr int T  = 30;
static constexpr int L  = 10;
static constexpr int NL = 10;
static constexpr int P  = 50;
static constexpr int PH = P / 2;   // 25 point-pairs
static constexpr int WARPS = 16;   // warps per block (512 threads)

__device__ float    g_acc[8];      // zero-init at module load; reset by last block
__device__ unsigned g_ticket = 0;

__device__ __forceinline__ float warp_sum(float v) {
#pragma unroll
    for (int o = 16; o; o >>= 1) v += __shfl_xor_sync(FULL, v, o);
    return v;
}
__device__ __forceinline__ float smooth_l1(float x) {
    float ax = fabsf(x);
    return ax < 1.f ? 0.5f * ax * ax : ax - 0.5f;
}

__device__ __forceinline__ unsigned long long pack2(float lo, float hi) {
    unsigned long long r;
    asm("mov.b64 %0, {%1, %2};" : "=l"(r) : "f"(lo), "f"(hi));
    return r;
}
__device__ __forceinline__ void unpack2(float& lo, float& hi, unsigned long long v) {
    asm("mov.b64 {%0, %1}, %2;" : "=f"(lo), "=f"(hi) : "l"(v));
}
__device__ __forceinline__ unsigned long long add2(unsigned long long a, unsigned long long b) {
    unsigned long long r;
    asm("add.rn.f32x2 %0, %1, %2;" : "=l"(r) : "l"(a), "l"(b));
    return r;
}
__device__ __forceinline__ unsigned long long mul2(unsigned long long a, unsigned long long b) {
    unsigned long long r;
    asm("mul.rn.f32x2 %0, %1, %2;" : "=l"(r) : "l"(a), "l"(b));
    return r;
}
__device__ __forceinline__ unsigned long long fma2(unsigned long long a, unsigned long long b,
                                                   unsigned long long c) {
    unsigned long long r;
    asm("fma.rn.f32x2 %0, %1, %2, %3;" : "=l"(r) : "l"(a), "l"(b), "l"(c));
    return r;
}

__global__ void __launch_bounds__(32 * WARPS)
pred_loss_kernel(const float* __restrict__ cls,
                 const float* __restrict__ reg,
                 const float* __restrict__ lane_cls,
                 const float* __restrict__ gt_preds,
                 const float* __restrict__ rot,
                 const float* __restrict__ orig,
                 const float* __restrict__ lane_feats,
                 const int* __restrict__ has_preds,   // bool widened to 4-byte
                 const int* __restrict__ lane_labels,
                 float* __restrict__ out,
                 int B)
{
    __shared__ float      s_acc[8];
    __shared__ ulonglong2 s_w[WARPS][PH];  // .x=(wx0,wx1) .y=(wy0,wy1) per point-pair

    const int lane = threadIdx.x & 31;
    const int wid  = threadIdx.x >> 5;
    const int b    = blockIdx.x * WARPS + wid;

    if (threadIdx.x < 8) s_acc[threadIdx.x] = 0.f;
    __syncthreads();

    if (b < B) {
        const int  t  = lane;
        const bool tv = (t < T);

        // --- has_preds / last index / mask --------------------------------
        bool hp = tv && (has_preds[b * T + (tv ? t : 0)] != 0);
        unsigned bits = __ballot_sync(FULL, hp);
        int   nhas    = __popc(bits);
        int   last_i  = 31 - __clz(bits | 1u);   // t=0 always set per setup
        float maskf   = (bits & ~1u) ? 1.f : 0.f;

        float2 gt = make_float2(0.f, 0.f);
        if (tv) gt = ((const float2*)gt_preds)[b * T + t];

        // --- per-mode per-t squared distances ------------------------------
        float rmx[M], rmy[M], d2m[M], sm[M];
#pragma unroll
        for (int m = 0; m < M; m++) {
            float2 r = make_float2(0.f, 0.f);
            if (tv) r = ((const float2*)reg)[(b * M + m) * T + t];
            rmx[m] = r.x; rmy[m] = r.y;
            float dx = r.x - gt.x, dy = r.y - gt.y;
            d2m[m] = tv ? fmaf(dx, dx, dy * dy) : 0.f;
            sm[m]  = d2m[m];
        }
        // 6 parallel butterflies: per-mode totals, bit-identical on all lanes
#pragma unroll
        for (int o = 16; o; o >>= 1) {
#pragma unroll
            for (int m = 0; m < M; m++)
                sm[m] += __shfl_xor_sync(FULL, sm[m], o);
        }
        float best_tot = sm[0]; int cls_tar = 0;
#pragma unroll
        for (int m = 1; m < M; m++)
            if (sm[m] < best_tot) { best_tot = sm[m]; cls_tar = m; }

        // end-point argmin: lane last_i holds the end d2 for every mode
        float best_end = d2m[0]; int my_min = 0;
#pragma unroll
        for (int m = 1; m < M; m++)
            if (d2m[m] < best_end) { best_end = d2m[m]; my_min = m; }
        int min_idx = __shfl_sync(FULL, my_min, last_i);

        // reg_sel = reg[b, min_idx, t]
        float rsx = rmx[0], rsy = rmy[0];
#pragma unroll
        for (int m = 1; m < M; m++) if (min_idx == m) { rsx = rmx[m]; rsy = rmy[m]; }

        // --- fused dual log-softmax (cls: lanes 0-5, lane_cls: lanes 16-25)
        int   label  = lane_labels[b];
        bool  valid  = (label != 90);
        int   lab    = valid ? label : 0;
        float validf = valid ? 1.f : 0.f;

        bool loC = (lane < M);
        bool hiC = (lane >= 16) && (lane < 16 + L);
        float val = -INFINITY;
        if (loC) val = cls[b * M + lane];
        if (hiC) val = lane_cls[b * L + (lane - 16)];

        float mx = val;
#pragma unroll
        for (int o = 8; o; o >>= 1) mx = fmaxf(mx, __shfl_xor_sync(FULL, mx, o));
        float ex = (loC || hiC) ? __expf(val - mx) : 0.f;
        float se = ex;
#pragma unroll
        for (int o = 8; o; o >>= 1) se += __shfl_xor_sync(FULL, se, o);

        float ctar = __shfl_sync(FULL, val, cls_tar);
        float ltar = __shfl_sync(FULL, val, 16 + lab);
        float cmx  = __shfl_sync(FULL, mx, 0);
        float lmx  = __shfl_sync(FULL, mx, 16);
        float cse  = __shfl_sync(FULL, se, 0);
        float lse  = __shfl_sync(FULL, se, 16);
        float nll      = -(ctar - cmx - __logf(cse));
        float lane_nll = -(ltar - lmx - __logf(lse));

        // --- rotate selected lane points -> shared (transposed pairs) -----
        float4 rr = ((const float4*)rot)[b];
        float2 og = ((const float2*)orig)[b];
        const float4* lf4 = (const float4*)(lane_feats + (size_t)(b * NL + lab) * P * 2);
        if (lane < PH) {
            float4 q = lf4[lane];   // points 2*lane (q.x,q.y) and 2*lane+1 (q.z,q.w)
            float wx0 = fmaf(q.x, rr.x, fmaf(q.y, rr.z, og.x));
            float wy0 = fmaf(q.x, rr.y, fmaf(q.y, rr.w, og.y));
            float wx1 = fmaf(q.z, rr.x, fmaf(q.w, rr.z, og.x));
            float wy1 = fmaf(q.z, rr.y, fmaf(q.w, rr.w, og.y));
            s_w[wid][lane] = make_ulonglong2(pack2(wx0, wx1), pack2(wy0, wy1));
        }
        __syncwarp(FULL);

        // --- min over P points: vector lanes = two points -----------------
        unsigned long long nrx2 = pack2(-rsx,  -rsx);
        unsigned long long nry2 = pack2(-rsy,  -rsy);
        unsigned long long ngx2 = pack2(-gt.x, -gt.x);
        unsigned long long ngy2 = pack2(-gt.y, -gt.y);
        float mr0 = INFINITY, mr1 = INFINITY, mg0 = INFINITY, mg1 = INFINITY;
#pragma unroll
        for (int i = 0; i < PH; i++) {
            ulonglong2 w = s_w[wid][i];
            unsigned long long dxr = add2(w.x, nrx2);
            unsigned long long dyr = add2(w.y, nry2);
            unsigned long long d2r = fma2(dxr, dxr, mul2(dyr, dyr));
            float a0, a1; unpack2(a0, a1, d2r);
            mr0 = fminf(mr0, a0); mr1 = fminf(mr1, a1);
            unsigned long long dxg = add2(w.x, ngx2);
            unsigned long long dyg = add2(w.y, ngy2);
            unsigned long long d2g = fma2(dxg, dxg, mul2(dyg, dyg));
            float g0, g1; unpack2(g0, g1, d2g);
            mg0 = fminf(mg0, g0); mg1 = fminf(mg1, g1);
        }
        float minr = fminf(mr0, mr1);
        float ming = fminf(mg0, mg1);

        float diff    = sqrtf(minr) - sqrtf(ming);
        float contrib = hp ? fmaxf(diff, 0.f) : 0.f;   // diff*(d_reg>=d_gt)*hasf

        // --- smooth-L1 regression loss ------------------------------------
        float wreg = hp ? maskf : 0.f;
        float regl = (smooth_l1(rsx - gt.x) + smooth_l1(rsy - gt.y)) * wreg;

        float sum_c = warp_sum(contrib);
        float sum_r = warp_sum(regl);

        if (lane == 0) {
            float per = sum_c / fmaxf((float)nhas, 1.f);
            atomicAdd(&s_acc[0], nll * maskf);
            atomicAdd(&s_acc[1], maskf);
            atomicAdd(&s_acc[2], sum_r);
            atomicAdd(&s_acc[3], (float)nhas * maskf);
            atomicAdd(&s_acc[4], lane_nll * (float)(lab + 1) * validf);
            atomicAdd(&s_acc[5], validf);
            atomicAdd(&s_acc[6], per * validf * maskf);
            atomicAdd(&s_acc[7], validf * maskf);
        }
    }
    __syncthreads();

    // --- block partial -> global, ticket, last block finalizes ------------
    if (threadIdx.x < 8) {
        atomicAdd(&g_acc[threadIdx.x], s_acc[threadIdx.x]);
        __threadfence();
    }
    __syncthreads();

    __shared__ bool s_last;
    if (threadIdx.x == 0) {
        unsigned tk = atomicAdd(&g_ticket, 1u);
        s_last = (tk == gridDim.x - 1);
    }
    __syncthreads();

    if (s_last) {
        if (threadIdx.x < 8) {
            __threadfence();
            s_acc[threadIdx.x] = atomicAdd(&g_acc[threadIdx.x], 0.f);  // coherent read
        }
        __syncthreads();
        if (threadIdx.x == 0) {
            out[0] = s_acc[0] / fmaxf(s_acc[1], 1.f);  // cls_loss
            out[1] = 1.f;
            out[2] = s_acc[2];                         // reg_loss
            out[3] = s_acc[3];                         // num_reg
            out[4] = s_acc[4];                         // lane_cls_loss
            out[5] = s_acc[5];                         // num_lane_cls
            out[6] = s_acc[6];                         // lane_off_loss
            out[7] = s_acc[7];                         // num_lane_off
        }
        // reset for next graph replay
        if (threadIdx.x < 8) atomicExch(&g_acc[threadIdx.x], 0.f);
        __syncthreads();
        if (threadIdx.x == 0) {
            __threadfence();
            atomicExch(&g_ticket, 0u);
        }
    }
}

extern "C" void kernel_launch(void* const* d_in, const int* in_sizes, int n_in,
                              void* d_out, int out_size)
{
    const float* cls        = (const float*)d_in[0];
    const float* reg        = (const float*)d_in[1];
    const float* lane_cls   = (const float*)d_in[2];
    const float* gt_preds   = (const float*)d_in[3];
    const float* rot        = (const float*)d_in[4];
    const float* orig       = (const float*)d_in[5];
    const float* lane_feats = (const float*)d_in[6];
    const int*   has_preds  = (const int*)d_in[7];
    const int*   lane_lab   = (const int*)d_in[8];

    int B = in_sizes[0] / M;   // cls is (B, M)
    int blocks = (B + WARPS - 1) / WARPS;
    pred_loss_kernel<<<blocks, 32 * WARPS>>>(cls, reg, lane_cls, gt_preds, rot,
                                             orig, lane_feats, has_preds,
                                             lane_lab, (float*)d_out, B);
}

// round 5
// speedup vs baseline: 1.1668x; 1.0520x over previous
#include <cuda_runtime.h>
#include <math.h>

#define FULL 0xffffffffu

static constexpr int M  = 6;
static constexpr int T  = 30;
static constexpr int L  = 10;
static constexpr int NL = 10;
static constexpr int P  = 50;
static constexpr int PH = P / 2;   // 25 point-pairs
static constexpr int WARPS = 8;    // warps per block (256 threads)

__device__ float    g_acc[8];      // zero-init at module load; reset by last block
__device__ unsigned g_ticket = 0;

__device__ __forceinline__ float smooth_l1(float x) {
    float ax = fabsf(x);
    return ax < 1.f ? 0.5f * ax * ax : ax - 0.5f;
}

__device__ __forceinline__ unsigned long long pack2(float lo, float hi) {
    unsigned long long r;
    asm("mov.b64 %0, {%1, %2};" : "=l"(r) : "f"(lo), "f"(hi));
    return r;
}
__device__ __forceinline__ void unpack2(float& lo, float& hi, unsigned long long v) {
    asm("mov.b64 {%0, %1}, %2;" : "=f"(lo), "=f"(hi) : "l"(v));
}
__device__ __forceinline__ unsigned long long add2(unsigned long long a, unsigned long long b) {
    unsigned long long r;
    asm("add.rn.f32x2 %0, %1, %2;" : "=l"(r) : "l"(a), "l"(b));
    return r;
}
__device__ __forceinline__ unsigned long long mul2(unsigned long long a, unsigned long long b) {
    unsigned long long r;
    asm("mul.rn.f32x2 %0, %1, %2;" : "=l"(r) : "l"(a), "l"(b));
    return r;
}
__device__ __forceinline__ unsigned long long fma2(unsigned long long a, unsigned long long b,
                                                   unsigned long long c) {
    unsigned long long r;
    asm("fma.rn.f32x2 %0, %1, %2, %3;" : "=l"(r) : "l"(a), "l"(b), "l"(c));
    return r;
}

__global__ void __launch_bounds__(32 * WARPS, 6)
pred_loss_kernel(const float* __restrict__ cls,
                 const float* __restrict__ reg,
                 const float* __restrict__ lane_cls,
                 const float* __restrict__ gt_preds,
                 const float* __restrict__ rot,
                 const float* __restrict__ orig,
                 const float* __restrict__ lane_feats,
                 const int* __restrict__ has_preds,   // bool widened to 4-byte
                 const int* __restrict__ lane_labels,
                 float* __restrict__ out,
                 int B)
{
    __shared__ float      s_acc[8];
    __shared__ ulonglong2 s_w[WARPS][PH];  // .x=(wx0,wx1) .y=(wy0,wy1) per point-pair

    const int lane = threadIdx.x & 31;
    const int wid  = threadIdx.x >> 5;
    const int b    = blockIdx.x * WARPS + wid;

    if (threadIdx.x < 8) s_acc[threadIdx.x] = 0.f;
    __syncthreads();

    if (b < B) {
        const int  t  = lane;
        const bool tv = (t < T);

        // --- kick off the dependent label -> lane_feats chain FIRST -------
        int   label  = lane_labels[b];
        bool  valid  = (label != 90);
        int   lab    = valid ? label : 0;
        float validf = valid ? 1.f : 0.f;

        // rotate selected lane points -> shared (transposed pairs);
        // warp-uniform skip when this row has no valid lane.
        if (valid) {
            float4 rr = ((const float4*)rot)[b];
            float2 og = ((const float2*)orig)[b];
            const float4* lf4 = (const float4*)(lane_feats + (size_t)(b * NL + lab) * P * 2);
            if (lane < PH) {
                float4 q = lf4[lane];   // points 2*lane and 2*lane+1
                float wx0 = fmaf(q.x, rr.x, fmaf(q.y, rr.z, og.x));
                float wy0 = fmaf(q.x, rr.y, fmaf(q.y, rr.w, og.y));
                float wx1 = fmaf(q.z, rr.x, fmaf(q.w, rr.z, og.x));
                float wy1 = fmaf(q.z, rr.y, fmaf(q.w, rr.w, og.y));
                s_w[wid][lane] = make_ulonglong2(pack2(wx0, wx1), pack2(wy0, wy1));
            }
        }
        __syncwarp(FULL);

        // --- has_preds / last index / mask --------------------------------
        bool hp = tv && (has_preds[b * T + (tv ? t : 0)] != 0);
        unsigned bits = __ballot_sync(FULL, hp);
        int   nhas    = __popc(bits);
        int   last_i  = 31 - __clz(bits | 1u);   // t=0 always set per setup
        float maskf   = (bits & ~1u) ? 1.f : 0.f;

        float2 gt = make_float2(0.f, 0.f);
        if (tv) gt = ((const float2*)gt_preds)[b * T + t];

        // --- per-mode per-t squared distances ------------------------------
        float rmx[M], rmy[M], d2m[M];
#pragma unroll
        for (int m = 0; m < M; m++) {
            float2 r = make_float2(0.f, 0.f);
            if (tv) r = ((const float2*)reg)[(b * M + m) * T + t];
            rmx[m] = r.x; rmy[m] = r.y;
            float dx = r.x - gt.x, dy = r.y - gt.y;
            d2m[m] = tv ? fmaf(dx, dx, dy * dy) : 0.f;
        }
        // 3 packed butterflies: per-mode totals, bit-identical on all lanes
        unsigned long long s01 = pack2(d2m[0], d2m[1]);
        unsigned long long s23 = pack2(d2m[2], d2m[3]);
        unsigned long long s45 = pack2(d2m[4], d2m[5]);
#pragma unroll
        for (int o = 16; o; o >>= 1) {
            s01 = add2(s01, __shfl_xor_sync(FULL, s01, o));
            s23 = add2(s23, __shfl_xor_sync(FULL, s23, o));
            s45 = add2(s45, __shfl_xor_sync(FULL, s45, o));
        }
        float sm[M];
        unpack2(sm[0], sm[1], s01);
        unpack2(sm[2], sm[3], s23);
        unpack2(sm[4], sm[5], s45);
        float best_tot = sm[0]; int cls_tar = 0;
#pragma unroll
        for (int m = 1; m < M; m++)
            if (sm[m] < best_tot) { best_tot = sm[m]; cls_tar = m; }

        // end-point argmin: lane last_i holds the end d2 for every mode
        float best_end = d2m[0]; int my_min = 0;
#pragma unroll
        for (int m = 1; m < M; m++)
            if (d2m[m] < best_end) { best_end = d2m[m]; my_min = m; }
        int min_idx = __shfl_sync(FULL, my_min, last_i);

        // reg_sel = reg[b, min_idx, t]
        float rsx = rmx[0], rsy = rmy[0];
#pragma unroll
        for (int m = 1; m < M; m++) if (min_idx == m) { rsx = rmx[m]; rsy = rmy[m]; }

        // --- fused dual log-softmax (cls: lanes 0-5, lane_cls: lanes 16-25)
        bool loC = (lane < M);
        bool hiC = (lane >= 16) && (lane < 16 + L);
        float val = -INFINITY;
        if (loC) val = cls[b * M + lane];
        if (hiC) val = lane_cls[b * L + (lane - 16)];

        float mx = val;
#pragma unroll
        for (int o = 8; o; o >>= 1) mx = fmaxf(mx, __shfl_xor_sync(FULL, mx, o));
        float ex = (loC || hiC) ? __expf(val - mx) : 0.f;
        float se = ex;
#pragma unroll
        for (int o = 8; o; o >>= 1) se += __shfl_xor_sync(FULL, se, o);

        float ctar = __shfl_sync(FULL, val, cls_tar);
        float ltar = __shfl_sync(FULL, val, 16 + lab);
        float cmx  = __shfl_sync(FULL, mx, 0);
        float lmx  = __shfl_sync(FULL, mx, 16);
        float cse  = __shfl_sync(FULL, se, 0);
        float lse  = __shfl_sync(FULL, se, 16);
        float nll      = -(ctar - cmx - __logf(cse));
        float lane_nll = -(ltar - lmx - __logf(lse));

        // --- min over P points (skip if row invalid: contrib weight is 0) -
        float contrib = 0.f;
        if (valid) {
            unsigned long long nrx2 = pack2(-rsx,  -rsx);
            unsigned long long nry2 = pack2(-rsy,  -rsy);
            unsigned long long ngx2 = pack2(-gt.x, -gt.x);
            unsigned long long ngy2 = pack2(-gt.y, -gt.y);
            float mr0 = INFINITY, mr1 = INFINITY, mg0 = INFINITY, mg1 = INFINITY;
#pragma unroll
            for (int i = 0; i < PH; i++) {
                ulonglong2 w = s_w[wid][i];
                unsigned long long dxr = add2(w.x, nrx2);
                unsigned long long dyr = add2(w.y, nry2);
                unsigned long long d2r = fma2(dxr, dxr, mul2(dyr, dyr));
                float a0, a1; unpack2(a0, a1, d2r);
                mr0 = fminf(mr0, a0); mr1 = fminf(mr1, a1);
                unsigned long long dxg = add2(w.x, ngx2);
                unsigned long long dyg = add2(w.y, ngy2);
                unsigned long long d2g = fma2(dxg, dxg, mul2(dyg, dyg));
                float g0, g1; unpack2(g0, g1, d2g);
                mg0 = fminf(mg0, g0); mg1 = fminf(mg1, g1);
            }
            float minr = fminf(mr0, mr1);
            float ming = fminf(mg0, mg1);
            float diff = sqrtf(minr) - sqrtf(ming);
            contrib    = hp ? fmaxf(diff, 0.f) : 0.f;  // diff*(d_reg>=d_gt)*hasf
        }

        // --- smooth-L1 regression loss ------------------------------------
        float wreg = hp ? maskf : 0.f;
        float regl = (smooth_l1(rsx - gt.x) + smooth_l1(rsy - gt.y)) * wreg;

        // packed dual warp-sum: (contrib, regl)
        unsigned long long cr = pack2(contrib, regl);
#pragma unroll
        for (int o = 16; o; o >>= 1)
            cr = add2(cr, __shfl_xor_sync(FULL, cr, o));
        float sum_c, sum_r;
        unpack2(sum_c, sum_r, cr);

        if (lane == 0) {
            float per = sum_c / fmaxf((float)nhas, 1.f);
            atomicAdd(&s_acc[0], nll * maskf);
            atomicAdd(&s_acc[1], maskf);
            atomicAdd(&s_acc[2], sum_r);
            atomicAdd(&s_acc[3], (float)nhas * maskf);
            atomicAdd(&s_acc[4], lane_nll * (float)(lab + 1) * validf);
            atomicAdd(&s_acc[5], validf);
            atomicAdd(&s_acc[6], per * validf * maskf);
            atomicAdd(&s_acc[7], validf * maskf);
        }
    }
    __syncthreads();

    // --- block partial -> global, ticket, last block finalizes ------------
    if (threadIdx.x < 8) {
        atomicAdd(&g_acc[threadIdx.x], s_acc[threadIdx.x]);
        __threadfence();
    }
    __syncthreads();

    __shared__ bool s_last;
    if (threadIdx.x == 0) {
        unsigned tk = atomicAdd(&g_ticket, 1u);
        s_last = (tk == gridDim.x - 1);
    }
    __syncthreads();

    if (s_last) {
        if (threadIdx.x < 8) {
            __threadfence();
            s_acc[threadIdx.x] = atomicAdd(&g_acc[threadIdx.x], 0.f);  // coherent read
        }
        __syncthreads();
        if (threadIdx.x == 0) {
            out[0] = s_acc[0] / fmaxf(s_acc[1], 1.f);  // cls_loss
            out[1] = 1.f;
            out[2] = s_acc[2];                         // reg_loss
            out[3] = s_acc[3];                         // num_reg
            out[4] = s_acc[4];                         // lane_cls_loss
            out[5] = s_acc[5];                         // num_lane_cls
            out[6] = s_acc[6];                         // lane_off_loss
            out[7] = s_acc[7];                         // num_lane_off
        }
        // reset for next graph replay
        if (threadIdx.x < 8) atomicExch(&g_acc[threadIdx.x], 0.f);
        __syncthreads();
        if (threadIdx.x == 0) {
            __threadfence();
            atomicExch(&g_ticket, 0u);
        }
    }
}

extern "C" void kernel_launch(void* const* d_in, const int* in_sizes, int n_in,
                              void* d_out, int out_size)
{
    const float* cls        = (const float*)d_in[0];
    const float* reg        = (const float*)d_in[1];
    const float* lane_cls   = (const float*)d_in[2];
    const float* gt_preds   = (const float*)d_in[3];
    const float* rot        = (const float*)d_in[4];
    const float* orig       = (const float*)d_in[5];
    const float* lane_feats = (const float*)d_in[6];
    const int*   has_preds  = (const int*)d_in[7];
    const int*   lane_lab   = (const int*)d_in[8];

    int B = in_sizes[0] / M;   // cls is (B, M)
    int blocks = (B + WARPS - 1) / WARPS;
    pred_loss_kernel<<<blocks, 32 * WARPS>>>(cls, reg, lane_cls, gt_preds, rot,
                                             orig, lane_feats, has_preds,
                                             lane_lab, (float*)d_out, B);
}

// round 6
// speedup vs baseline: 1.1743x; 1.0064x over previous
#include <cuda_runtime.h>
#include <math.h>

#define FULL 0xffffffffu

static constexpr int M  = 6;
static constexpr int T  = 30;
static constexpr int L  = 10;
static constexpr int NL = 10;
static constexpr int P  = 50;
static constexpr int PH = P / 2;   // 25 point-pairs
static constexpr int WARPS = 8;    // warps per block (256 threads)

__device__ float    g_acc[8];      // zero-init at module load; reset by last block
__device__ unsigned g_ticket = 0;

__device__ __forceinline__ float smooth_l1(float x) {
    float ax = fabsf(x);
    return ax < 1.f ? 0.5f * ax * ax : ax - 0.5f;
}

__device__ __forceinline__ unsigned long long pack2(float lo, float hi) {
    unsigned long long r;
    asm("mov.b64 %0, {%1, %2};" : "=l"(r) : "f"(lo), "f"(hi));
    return r;
}
__device__ __forceinline__ void unpack2(float& lo, float& hi, unsigned long long v) {
    asm("mov.b64 {%0, %1}, %2;" : "=f"(lo), "=f"(hi) : "l"(v));
}
__device__ __forceinline__ unsigned long long add2(unsigned long long a, unsigned long long b) {
    unsigned long long r;
    asm("add.rn.f32x2 %0, %1, %2;" : "=l"(r) : "l"(a), "l"(b));
    return r;
}
__device__ __forceinline__ unsigned long long mul2(unsigned long long a, unsigned long long b) {
    unsigned long long r;
    asm("mul.rn.f32x2 %0, %1, %2;" : "=l"(r) : "l"(a), "l"(b));
    return r;
}
__device__ __forceinline__ unsigned long long fma2(unsigned long long a, unsigned long long b,
                                                   unsigned long long c) {
    unsigned long long r;
    asm("fma.rn.f32x2 %0, %1, %2, %3;" : "=l"(r) : "l"(a), "l"(b), "l"(c));
    return r;
}

__global__ void __launch_bounds__(32 * WARPS, 6)
pred_loss_kernel(const float* __restrict__ cls,
                 const float* __restrict__ reg,
                 const float* __restrict__ lane_cls,
                 const float* __restrict__ gt_preds,
                 const float* __restrict__ rot,
                 const float* __restrict__ orig,
                 const float* __restrict__ lane_feats,
                 const int* __restrict__ has_preds,   // bool widened to 4-byte
                 const int* __restrict__ lane_labels,
                 float* __restrict__ out,
                 int B)
{
    __shared__ float s_acc[8];
    __shared__ ulonglong2         s_xy[WARPS][PH]; // (wx0,wx1),(wy0,wy1)
    __shared__ unsigned long long s_q [WARPS][PH]; // (|w0|^2, |w1|^2)

    const int lane = threadIdx.x & 31;
    const int wid  = threadIdx.x >> 5;
    const int b    = blockIdx.x * WARPS + wid;

    if (threadIdx.x < 8) s_acc[threadIdx.x] = 0.f;
    __syncthreads();

    if (b < B) {
        const int  t  = lane;
        const bool tv = (t < T);

        // --- kick off the dependent label -> lane_feats chain FIRST -------
        int   label  = lane_labels[b];
        bool  valid  = (label != 90);
        int   lab    = valid ? label : 0;
        float validf = valid ? 1.f : 0.f;

        // rotate selected lane points -> shared (transposed pairs + |w|^2)
        if (valid) {
            float4 rr = ((const float4*)rot)[b];
            float2 og = ((const float2*)orig)[b];
            const float4* lf4 = (const float4*)(lane_feats + (size_t)(b * NL + lab) * P * 2);
            if (lane < PH) {
                float4 q = lf4[lane];   // points 2*lane and 2*lane+1
                float wx0 = fmaf(q.x, rr.x, fmaf(q.y, rr.z, og.x));
                float wy0 = fmaf(q.x, rr.y, fmaf(q.y, rr.w, og.y));
                float wx1 = fmaf(q.z, rr.x, fmaf(q.w, rr.z, og.x));
                float wy1 = fmaf(q.z, rr.y, fmaf(q.w, rr.w, og.y));
                s_xy[wid][lane] = make_ulonglong2(pack2(wx0, wx1), pack2(wy0, wy1));
                s_q [wid][lane] = pack2(fmaf(wx0, wx0, wy0 * wy0),
                                        fmaf(wx1, wx1, wy1 * wy1));
            }
        }
        __syncwarp(FULL);

        // --- has_preds / last index / mask --------------------------------
        bool hp = tv && (has_preds[b * T + (tv ? t : 0)] != 0);
        unsigned bits = __ballot_sync(FULL, hp);
        int   nhas    = __popc(bits);
        int   last_i  = 31 - __clz(bits | 1u);   // t=0 always set per setup
        float maskf   = (bits & ~1u) ? 1.f : 0.f;

        float2 gt = make_float2(0.f, 0.f);
        if (tv) gt = ((const float2*)gt_preds)[b * T + t];

        // --- per-mode per-t squared distances (mode-pair packed) -----------
        // invalid lanes have r=gt=(0,0) -> d2=0 naturally, no selects needed
        float rmx[M], rmy[M];
        float2 rv[M];
#pragma unroll
        for (int m = 0; m < M; m++) {
            float2 r = make_float2(0.f, 0.f);
            if (tv) r = ((const float2*)reg)[(b * M + m) * T + t];
            rv[m] = r; rmx[m] = r.x; rmy[m] = r.y;
        }
        unsigned long long ngx = pack2(-gt.x, -gt.x);
        unsigned long long ngy = pack2(-gt.y, -gt.y);
        unsigned long long s01, s23, s45;
        {
            unsigned long long dx, dy;
            dx = add2(pack2(rv[0].x, rv[1].x), ngx);
            dy = add2(pack2(rv[0].y, rv[1].y), ngy);
            s01 = fma2(dx, dx, mul2(dy, dy));
            dx = add2(pack2(rv[2].x, rv[3].x), ngx);
            dy = add2(pack2(rv[2].y, rv[3].y), ngy);
            s23 = fma2(dx, dx, mul2(dy, dy));
            dx = add2(pack2(rv[4].x, rv[5].x), ngx);
            dy = add2(pack2(rv[4].y, rv[5].y), ngy);
            s45 = fma2(dx, dx, mul2(dy, dy));
        }
        float d2m[M];
        unpack2(d2m[0], d2m[1], s01);
        unpack2(d2m[2], d2m[3], s23);
        unpack2(d2m[4], d2m[5], s45);

        // 3 packed butterflies: per-mode totals, bit-identical on all lanes
#pragma unroll
        for (int o = 16; o; o >>= 1) {
            s01 = add2(s01, __shfl_xor_sync(FULL, s01, o));
            s23 = add2(s23, __shfl_xor_sync(FULL, s23, o));
            s45 = add2(s45, __shfl_xor_sync(FULL, s45, o));
        }
        float sm[M];
        unpack2(sm[0], sm[1], s01);
        unpack2(sm[2], sm[3], s23);
        unpack2(sm[4], sm[5], s45);
        float best_tot = sm[0]; int cls_tar = 0;
#pragma unroll
        for (int m = 1; m < M; m++)
            if (sm[m] < best_tot) { best_tot = sm[m]; cls_tar = m; }

        // end-point argmin: lane last_i holds the end d2 for every mode
        float best_end = d2m[0]; int my_min = 0;
#pragma unroll
        for (int m = 1; m < M; m++)
            if (d2m[m] < best_end) { best_end = d2m[m]; my_min = m; }
        int min_idx = __shfl_sync(FULL, my_min, last_i);

        // reg_sel = reg[b, min_idx, t]
        float rsx = rmx[0], rsy = rmy[0];
#pragma unroll
        for (int m = 1; m < M; m++) if (min_idx == m) { rsx = rmx[m]; rsy = rmy[m]; }

        // --- fused dual log-softmax (cls: lanes 0-5, lane_cls: lanes 16-25)
        bool loC = (lane < M);
        bool hiC = (lane >= 16) && (lane < 16 + L);
        float val = -INFINITY;
        if (loC) val = cls[b * M + lane];
        if (hiC) val = lane_cls[b * L + (lane - 16)];

        float mx = val;
#pragma unroll
        for (int o = 8; o; o >>= 1) mx = fmaxf(mx, __shfl_xor_sync(FULL, mx, o));
        float ex = (loC || hiC) ? __expf(val - mx) : 0.f;
        float se = ex;
#pragma unroll
        for (int o = 8; o; o >>= 1) se += __shfl_xor_sync(FULL, se, o);

        float ctar = __shfl_sync(FULL, val, cls_tar);
        float ltar = __shfl_sync(FULL, val, 16 + lab);
        float cmx  = __shfl_sync(FULL, mx, 0);
        float lmx  = __shfl_sync(FULL, mx, 16);
        float cse  = __shfl_sync(FULL, se, 0);
        float lse  = __shfl_sync(FULL, se, 16);
        float nll      = -(ctar - cmx - __logf(cse));
        float lane_nll = -(ltar - lmx - __logf(lse));

        // --- min over P points via hoisted ||c||^2 identity ----------------
        // min_p ||w-c||^2 = min_p(|w|^2 - 2 w.c) + |c|^2
        float contrib = 0.f;
        if (valid) {
            unsigned long long arx = pack2(-2.f * rsx,  -2.f * rsx);
            unsigned long long ary = pack2(-2.f * rsy,  -2.f * rsy);
            unsigned long long agx = pack2(-2.f * gt.x, -2.f * gt.x);
            unsigned long long agy = pack2(-2.f * gt.y, -2.f * gt.y);
            float Cr = fmaf(rsx, rsx, rsy * rsy);
            float Cg = fmaf(gt.x, gt.x, gt.y * gt.y);
            float mr0 = INFINITY, mr1 = INFINITY, mg0 = INFINITY, mg1 = INFINITY;
#pragma unroll
            for (int i = 0; i < PH; i++) {
                ulonglong2 xy = s_xy[wid][i];
                unsigned long long q = s_q[wid][i];
                unsigned long long dr = fma2(xy.y, ary, fma2(xy.x, arx, q));
                unsigned long long dg = fma2(xy.y, agy, fma2(xy.x, agx, q));
                float a0, a1; unpack2(a0, a1, dr);
                mr0 = fminf(mr0, a0); mr1 = fminf(mr1, a1);
                float g0, g1; unpack2(g0, g1, dg);
                mg0 = fminf(mg0, g0); mg1 = fminf(mg1, g1);
            }
            float minr = fmaxf(fminf(mr0, mr1) + Cr, 0.f);
            float ming = fmaxf(fminf(mg0, mg1) + Cg, 0.f);
            float diff = sqrtf(minr) - sqrtf(ming);
            contrib    = hp ? fmaxf(diff, 0.f) : 0.f;  // diff*(d_reg>=d_gt)*hasf
        }

        // --- smooth-L1 regression loss ------------------------------------
        float wreg = hp ? maskf : 0.f;
        float regl = (smooth_l1(rsx - gt.x) + smooth_l1(rsy - gt.y)) * wreg;

        // packed dual warp-sum: (contrib, regl)
        unsigned long long cr = pack2(contrib, regl);
#pragma unroll
        for (int o = 16; o; o >>= 1)
            cr = add2(cr, __shfl_xor_sync(FULL, cr, o));
        float sum_c, sum_r;
        unpack2(sum_c, sum_r, cr);

        if (lane == 0) {
            float per = sum_c / fmaxf((float)nhas, 1.f);
            atomicAdd(&s_acc[0], nll * maskf);
            atomicAdd(&s_acc[1], maskf);
            atomicAdd(&s_acc[2], sum_r);
            atomicAdd(&s_acc[3], (float)nhas * maskf);
            atomicAdd(&s_acc[4], lane_nll * (float)(lab + 1) * validf);
            atomicAdd(&s_acc[5], validf);
            atomicAdd(&s_acc[6], per * validf * maskf);
            atomicAdd(&s_acc[7], validf * maskf);
        }
    }
    __syncthreads();

    // --- block partial -> global, ticket, last block finalizes ------------
    if (threadIdx.x < 8) {
        atomicAdd(&g_acc[threadIdx.x], s_acc[threadIdx.x]);
        __threadfence();
    }
    __syncthreads();

    __shared__ bool s_last;
    if (threadIdx.x == 0) {
        unsigned tk = atomicAdd(&g_ticket, 1u);
        s_last = (tk == gridDim.x - 1);
    }
    __syncthreads();

    if (s_last) {
        if (threadIdx.x < 8) {
            __threadfence();
            s_acc[threadIdx.x] = atomicAdd(&g_acc[threadIdx.x], 0.f);  // coherent read
        }
        __syncthreads();
        if (threadIdx.x == 0) {
            out[0] = s_acc[0] / fmaxf(s_acc[1], 1.f);  // cls_loss
            out[1] = 1.f;
            out[2] = s_acc[2];                         // reg_loss
            out[3] = s_acc[3];                         // num_reg
            out[4] = s_acc[4];                         // lane_cls_loss
            out[5] = s_acc[5];                         // num_lane_cls
            out[6] = s_acc[6];                         // lane_off_loss
            out[7] = s_acc[7];                         // num_lane_off
        }
        // reset for next graph replay
        if (threadIdx.x < 8) atomicExch(&g_acc[threadIdx.x], 0.f);
        __syncthreads();
        if (threadIdx.x == 0) {
            __threadfence();
            atomicExch(&g_ticket, 0u);
        }
    }
}

extern "C" void kernel_launch(void* const* d_in, const int* in_sizes, int n_in,
                              void* d_out, int out_size)
{
    const float* cls        = (const float*)d_in[0];
    const float* reg        = (const float*)d_in[1];
    const float* lane_cls   = (const float*)d_in[2];
    const float* gt_preds   = (const float*)d_in[3];
    const float* rot        = (const float*)d_in[4];
    const float* orig       = (const float*)d_in[5];
    const float* lane_feats = (const float*)d_in[6];
    const int*   has_preds  = (const int*)d_in[7];
    const int*   lane_lab   = (const int*)d_in[8];

    int B = in_sizes[0] / M;   // cls is (B, M)
    int blocks = (B + WARPS - 1) / WARPS;
    pred_loss_kernel<<<blocks, 32 * WARPS>>>(cls, reg, lane_cls, gt_preds, rot,
                                             orig, lane_feats, has_preds,
                                             lane_lab, (float*)d_out, B);
}